// round 2
// baseline (speedup 1.0000x reference)
#include <cuda_runtime.h>
#include <cstdint>
#include <cstddef>

// Problem dims
#define BDIM 4096
#define TDIM 128
#define DDIM 64
#define HDIM 100
#define G4   400          // 4*H
#define NCLS 8
#define M1   (BDIM * TDIM)   // 524288 rows

// ---------------- scratch (device globals; no allocation allowed) ----------
__device__ float g_xp[(size_t)M1 * G4];     // 800 MB, reused by both layers
__device__ float g_h1[(size_t)M1 * HDIM];   // 200 MB, relu(h) of layer 1
__device__ float g_last[BDIM * HDIM];       // relu(h_T) of layer 2

// ---------------- activation helpers ----------------
__device__ __forceinline__ float sigm(float x) {
    return __fdividef(1.0f, 1.0f + __expf(-x));
}
__device__ __forceinline__ float tanh_fast(float x) {
    float ax = fabsf(x);
    float e  = __expf(-2.0f * ax);            // e in (0,1], no overflow
    float r  = (1.0f - e) * __fdividef(1.0f, 1.0f + e);
    return copysignf(r, x);
}

// ---------------- input-projection GEMM: g_xp = X @ W^T + (ba+bb) ----------
// X: [M1, K], W: [400, K]. Block: 400 threads, 64-row tiles, 8x8 register tile.
template <int K>
__global__ __launch_bounds__(400) void xproj_kernel(
    const float* __restrict__ X, const float* __restrict__ W,
    const float* __restrict__ ba, const float* __restrict__ bb)
{
    constexpr int KP = K + 1;                 // pad to kill bank conflicts
    extern __shared__ float sm[];
    float* Ws = sm;                           // [400][KP]
    float* Xs = sm + G4 * KP;                 // [64][KP]
    __shared__ float bs[G4];

    const int tid = threadIdx.x;

    for (int i = tid; i < G4 * K; i += 400) {
        int g = i / K, k = i - g * K;
        Ws[g * KP + k] = W[i];
    }
    for (int i = tid; i < G4; i += 400) bs[i] = ba[i] + bb[i];
    __syncthreads();

    const int cj = tid % 50;                  // col base (cols cj + cc*50)
    const int ri = tid / 50;                  // row base (rows ri + rr*8)
    const int ntiles = M1 / 64;

    for (int tile = blockIdx.x; tile < ntiles; tile += gridDim.x) {
        const float* Xt = X + (size_t)tile * (64 * K);
        for (int i = tid; i < 64 * K; i += 400) {
            int r = i / K, k = i - r * K;
            Xs[r * KP + k] = Xt[i];
        }
        __syncthreads();

        float acc[8][8];
        #pragma unroll
        for (int rr = 0; rr < 8; rr++)
            #pragma unroll
            for (int cc = 0; cc < 8; cc++) acc[rr][cc] = 0.0f;

        #pragma unroll 2
        for (int k = 0; k < K; k++) {
            float xv[8], wv[8];
            #pragma unroll
            for (int rr = 0; rr < 8; rr++) xv[rr] = Xs[(ri + rr * 8) * KP + k];
            #pragma unroll
            for (int cc = 0; cc < 8; cc++) wv[cc] = Ws[(cj + cc * 50) * KP + k];
            #pragma unroll
            for (int rr = 0; rr < 8; rr++)
                #pragma unroll
                for (int cc = 0; cc < 8; cc++)
                    acc[rr][cc] = fmaf(xv[rr], wv[cc], acc[rr][cc]);
        }

        float* XPt = g_xp + (size_t)tile * (64 * G4);
        #pragma unroll
        for (int rr = 0; rr < 8; rr++) {
            #pragma unroll
            for (int cc = 0; cc < 8; cc++) {
                int col = cj + cc * 50;
                XPt[(ri + rr * 8) * G4 + col] = acc[rr][cc] + bs[col];
            }
        }
        __syncthreads();
    }
}

// ---------------- recurrent scan ----------------
// gates[b][g] = g_xp[b][t][g] + sum_k h[b][k] * Whh[g][k]
// Block: 32 batch rows, 400 threads. Whh k-major in shared (Ws[k*400+g]),
// h in shared (Hs[u*32+b]), c in registers. Thread tile: 4 batch x 2 units x 4 gates.
// mode==1: write relu(h) for all t into g_h1. mode==2: write relu(h_{T-1}) to g_last.
__global__ __launch_bounds__(400) void lstm_scan_kernel(
    const float* __restrict__ Whh, int mode)
{
    extern __shared__ float sm[];
    float* Ws = sm;                   // [100][400], k-major
    float* Hs = sm + HDIM * G4;       // [100][32]

    const int tid = threadIdx.x;
    const int b0  = blockIdx.x * 32;

    for (int i = tid; i < HDIM * G4; i += 400) {
        int g = i / HDIM, k = i - g * HDIM;
        Ws[k * G4 + g] = Whh[i];
    }
    for (int i = tid; i < HDIM * 32; i += 400) Hs[i] = 0.0f;
    __syncthreads();

    const int bi   = tid & 7;         // batch group (4 rows)
    const int uj   = tid >> 3;        // 0..49 -> units 2uj, 2uj+1
    const int bloc = bi * 4;

    float c[4][2];
    #pragma unroll
    for (int bb = 0; bb < 4; bb++) { c[bb][0] = 0.0f; c[bb][1] = 0.0f; }

    const float* wp = Ws + uj * 2;
    const float* hp = Hs + bloc;

    for (int t = 0; t < TDIM; t++) {
        float acc[4][4][2];
        // init accumulators from precomputed x-projection
        #pragma unroll
        for (int bb = 0; bb < 4; bb++) {
            const float* xp = g_xp + ((size_t)(b0 + bloc + bb) * TDIM + t) * G4 + uj * 2;
            #pragma unroll
            for (int gt = 0; gt < 4; gt++) {
                float2 v = *(const float2*)(xp + gt * HDIM);
                acc[gt][bb][0] = v.x;
                acc[gt][bb][1] = v.y;
            }
        }
        // recurrent GEMM tile
        #pragma unroll 2
        for (int k = 0; k < HDIM; k++) {
            float4 hv = *(const float4*)(hp + k * 32);
            float hva[4] = {hv.x, hv.y, hv.z, hv.w};
            #pragma unroll
            for (int gt = 0; gt < 4; gt++) {
                float2 wv = *(const float2*)(wp + k * G4 + gt * HDIM);
                #pragma unroll
                for (int bb = 0; bb < 4; bb++) {
                    acc[gt][bb][0] = fmaf(hva[bb], wv.x, acc[gt][bb][0]);
                    acc[gt][bb][1] = fmaf(hva[bb], wv.y, acc[gt][bb][1]);
                }
            }
        }
        __syncthreads();   // all reads of Hs(t-1) done

        float hval[4][2];
        #pragma unroll
        for (int bb = 0; bb < 4; bb++) {
            #pragma unroll
            for (int uu = 0; uu < 2; uu++) {
                float iv = sigm(acc[0][bb][uu]);
                float fv = sigm(acc[1][bb][uu]);
                float gv = tanh_fast(acc[2][bb][uu]);
                float ov = sigm(acc[3][bb][uu]);
                float cv = fmaf(fv, c[bb][uu], iv * gv);
                c[bb][uu] = cv;
                hval[bb][uu] = ov * tanh_fast(cv);
            }
        }
        // write new h (raw) into shared state
        #pragma unroll
        for (int uu = 0; uu < 2; uu++) {
            float4 v = make_float4(hval[0][uu], hval[1][uu], hval[2][uu], hval[3][uu]);
            *(float4*)(Hs + (uj * 2 + uu) * 32 + bloc) = v;
        }
        // outputs (relu applied outside the recurrence, matching the reference)
        if (mode == 1) {
            #pragma unroll
            for (int bb = 0; bb < 4; bb++) {
                float2 v = make_float2(fmaxf(hval[bb][0], 0.0f), fmaxf(hval[bb][1], 0.0f));
                *(float2*)(g_h1 + ((size_t)(b0 + bloc + bb) * TDIM + t) * HDIM + uj * 2) = v;
            }
        } else if (t == TDIM - 1) {
            #pragma unroll
            for (int bb = 0; bb < 4; bb++) {
                float2 v = make_float2(fmaxf(hval[bb][0], 0.0f), fmaxf(hval[bb][1], 0.0f));
                *(float2*)(g_last + (b0 + bloc + bb) * HDIM + uj * 2) = v;
            }
        }
        __syncthreads();   // Hs(t) visible before next step
    }
}

// ---------------- head: fc(8) + softmax ----------------
__global__ void head_kernel(const float* __restrict__ wfc,
                            const float* __restrict__ bfc,
                            float* __restrict__ out)
{
    int b = blockIdx.x * blockDim.x + threadIdx.x;
    if (b >= BDIM) return;
    const float* lr = g_last + b * HDIM;
    float lo[NCLS];
    #pragma unroll
    for (int cc = 0; cc < NCLS; cc++) {
        float s = bfc[cc];
        const float* wr = wfc + cc * HDIM;
        for (int u = 0; u < HDIM; u++) s = fmaf(lr[u], wr[u], s);
        lo[cc] = s;
    }
    float m = lo[0];
    #pragma unroll
    for (int cc = 1; cc < NCLS; cc++) m = fmaxf(m, lo[cc]);
    float sum = 0.0f;
    #pragma unroll
    for (int cc = 0; cc < NCLS; cc++) { lo[cc] = __expf(lo[cc] - m); sum += lo[cc]; }
    float inv = __fdividef(1.0f, sum);
    #pragma unroll
    for (int cc = 0; cc < NCLS; cc++) out[b * NCLS + cc] = lo[cc] * inv;
}

// ---------------- launch ----------------
extern "C" void kernel_launch(void* const* d_in, const int* in_sizes, int n_in,
                              void* d_out, int out_size)
{
    (void)in_sizes; (void)n_in; (void)out_size;
    const float* x     = (const float*)d_in[0];
    const float* w_ih1 = (const float*)d_in[1];
    const float* w_hh1 = (const float*)d_in[2];
    const float* b_ih1 = (const float*)d_in[3];
    const float* b_hh1 = (const float*)d_in[4];
    const float* w_ih2 = (const float*)d_in[5];
    const float* w_hh2 = (const float*)d_in[6];
    const float* b_ih2 = (const float*)d_in[7];
    const float* b_hh2 = (const float*)d_in[8];
    const float* w_fc  = (const float*)d_in[9];
    const float* b_fc  = (const float*)d_in[10];

    const int S64  = (G4 * 65  + 64 * 65)  * 4;   // 120640 B
    const int S100 = (G4 * 101 + 64 * 101) * 4;   // 187456 B
    const int SSC  = (HDIM * G4 + HDIM * 32) * 4; // 172800 B

    cudaFuncSetAttribute(xproj_kernel<64>,  cudaFuncAttributeMaxDynamicSharedMemorySize, S64);
    cudaFuncSetAttribute(xproj_kernel<100>, cudaFuncAttributeMaxDynamicSharedMemorySize, S100);
    cudaFuncSetAttribute(lstm_scan_kernel,  cudaFuncAttributeMaxDynamicSharedMemorySize, SSC);

    void* h1_ptr = nullptr;
    cudaGetSymbolAddress(&h1_ptr, g_h1);

    // layer 1
    xproj_kernel<64><<<148, 400, S64>>>(x, w_ih1, b_ih1, b_hh1);
    lstm_scan_kernel<<<128, 400, SSC>>>(w_hh1, 1);
    // layer 2
    xproj_kernel<100><<<148, 400, S100>>>((const float*)h1_ptr, w_ih2, b_ih2, b_hh2);
    lstm_scan_kernel<<<128, 400, SSC>>>(w_hh2, 2);
    // head
    head_kernel<<<(BDIM + 255) / 256, 256>>>(w_fc, b_fc, (float*)d_out);
}

// round 5
// speedup vs baseline: 1.3534x; 1.3534x over previous
#include <cuda_runtime.h>
#include <cuda_bf16.h>
#include <cstdint>
#include <cstddef>

// Problem dims
#define BDIM 4096
#define TDIM 128
#define DDIM 64
#define HDIM 100
#define G4   400          // 4*H
#define NCLS 8
#define M1   (BDIM * TDIM)   // 524288 rows

// ---------------- scratch (device globals; no allocation allowed) ----------
__device__ __align__(16) float g_xp[(size_t)M1 * G4];     // 800 MB, reused by both layers
__device__ __align__(16) float g_h1[(size_t)M1 * HDIM];   // 200 MB, relu(h) of layer 1
__device__ __align__(16) float g_last[BDIM * HDIM];       // relu(h_T) of layer 2

// ---------------- helpers ----------------
__device__ __forceinline__ float sigm(float x) {
    return __fdividef(1.0f, 1.0f + __expf(-x));
}
__device__ __forceinline__ float tanh_fast(float x) {
    float ax = fabsf(x);
    float e  = __expf(-2.0f * ax);
    float r  = (1.0f - e) * __fdividef(1.0f, 1.0f + e);
    return copysignf(r, x);
}

__device__ __forceinline__ uint32_t pack_bf2(float a, float b) {
    __nv_bfloat162 p = __floats2bfloat162_rn(a, b);   // .x = a (low), .y = b (high)
    return *reinterpret_cast<uint32_t*>(&p);
}

// m16n8k16 row.col bf16 MMA with fp32 accumulate (sm_80+ path; HMMA on Blackwell)
__device__ __forceinline__ void mma16816(float c[4], const uint32_t a[4], const uint32_t b[2]) {
    asm volatile(
        "mma.sync.aligned.m16n8k16.row.col.f32.bf16.bf16.f32 "
        "{%0,%1,%2,%3}, {%4,%5,%6,%7}, {%8,%9}, {%0,%1,%2,%3};"
        : "+f"(c[0]), "+f"(c[1]), "+f"(c[2]), "+f"(c[3])
        : "r"(a[0]), "r"(a[1]), "r"(a[2]), "r"(a[3]), "r"(b[0]), "r"(b[1]));
}

// ======================================================================
// Tensor-core (mma.sync) input projection: g_xp = X @ W^T + (ba+bb)
// bf16 hi/lo split (3 MMAs). Grid 148: blockIdx&1 picks gate half (200 cols),
// 74 CTAs sweep the 4096 row tiles of 128.
// Block = 384 threads: warps 0-7 compute (16 rows each), warps 8-11 convert
// the next X tile into the other smem buffer.
// ======================================================================
template <int K>
__device__ __forceinline__ void convert_tile(const float* __restrict__ Xt,
                                             char* Hi, char* Lo, int t0, int nthr)
{
    constexpr int KP = (K == 64) ? 72 : 120;
    constexpr int KQ = K / 4;
    for (int i4 = t0; i4 < 128 * KQ; i4 += nthr) {
        int r = i4 / KQ, kq = i4 - r * KQ;
        float4 v = *(const float4*)(Xt + (size_t)r * K + kq * 4);
        float h0 = __bfloat162float(__float2bfloat16(v.x));
        float h1 = __bfloat162float(__float2bfloat16(v.y));
        float h2 = __bfloat162float(__float2bfloat16(v.z));
        float h3 = __bfloat162float(__float2bfloat16(v.w));
        uint32_t* ph = (uint32_t*)(Hi + (r * KP + kq * 4) * 2);
        uint32_t* pl = (uint32_t*)(Lo + (r * KP + kq * 4) * 2);
        ph[0] = pack_bf2(h0, h1);
        ph[1] = pack_bf2(h2, h3);
        pl[0] = pack_bf2(v.x - h0, v.y - h1);
        pl[1] = pack_bf2(v.z - h2, v.w - h3);
    }
}

template <int K>
__global__ __launch_bounds__(384) void xproj_mma(
    const float* __restrict__ X, const float* __restrict__ W,
    const float* __restrict__ ba, const float* __restrict__ bb)
{
    constexpr int KP     = (K == 64) ? 72 : 120;   // smem row stride (conflict-free)
    constexpr int KSTEPS = (K + 15) / 16;          // 4 or 7
    constexpr int NH     = 200;
    constexpr int WB     = NH  * KP * 2;           // bytes per W buffer (hi or lo)
    constexpr int XB     = 128 * KP * 2;           // bytes per X buffer (hi or lo)

    extern __shared__ char sm[];
    float* bs = (float*)sm;                        // [200] bias
    char* Whi = sm + 1024;
    char* Wlo = Whi + WB;
    char* Xbase = Wlo + WB;                        // 2 double-buffered (hi,lo) pairs

    const int tid  = threadIdx.x;
    const int wid  = tid >> 5;
    const int lane = tid & 31;
    const int g    = lane >> 2;        // group id (0..7)
    const int t4   = lane & 3;         // thread in group
    const int hf   = blockIdx.x & 1;   // gate half
    const int cta  = blockIdx.x >> 1;  // 0..73

    // zero whole data region (covers K->KSTEPS*16 zero padding)
    {
        uint32_t* z = (uint32_t*)Whi;
        int tot = (2 * WB + 4 * XB) / 4;
        for (int i = tid; i < tot; i += 384) z[i] = 0;
    }
    __syncthreads();

    // convert W (hi/lo) + bias, all threads
    {
        constexpr int KQ = K / 4;
        for (int i4 = tid; i4 < NH * KQ; i4 += 384) {
            int n = i4 / KQ, kq = i4 - n * KQ;
            float4 v = *(const float4*)(W + (size_t)(hf * NH + n) * K + kq * 4);
            float h0 = __bfloat162float(__float2bfloat16(v.x));
            float h1 = __bfloat162float(__float2bfloat16(v.y));
            float h2 = __bfloat162float(__float2bfloat16(v.z));
            float h3 = __bfloat162float(__float2bfloat16(v.w));
            uint32_t* ph = (uint32_t*)(Whi + (n * KP + kq * 4) * 2);
            uint32_t* pl = (uint32_t*)(Wlo + (n * KP + kq * 4) * 2);
            ph[0] = pack_bf2(h0, h1);
            ph[1] = pack_bf2(h2, h3);
            pl[0] = pack_bf2(v.x - h0, v.y - h1);
            pl[1] = pack_bf2(v.z - h2, v.w - h3);
        }
        for (int n = tid; n < NH; n += 384) {
            int gg = hf * NH + n;
            bs[n] = ba[gg] + bb[gg];
        }
    }
    // first X tile into buffer 0, all threads
    convert_tile<K>(X + (size_t)cta * 128 * K, Xbase, Xbase + XB, tid, 384);

    const uint32_t* Wh32 = (const uint32_t*)Whi;
    const uint32_t* Wl32 = (const uint32_t*)Wlo;
    const int m0 = wid * 16;

    int par = 0;
    for (int tile = cta; tile < 4096; tile += 74) {
        __syncthreads();   // buf[par] ready; previous compute done with buf[par^1]

        if (wid >= 8) {
            // converter warps: fill buf[par^1] with tile+74
            int nt = tile + 74;
            if (nt < 4096) {
                char* Hi = Xbase + (par ^ 1) * (2 * XB);
                convert_tile<K>(X + (size_t)nt * 128 * K, Hi, Hi + XB, tid - 256, 128);
            }
        } else {
            const uint32_t* Xh = (const uint32_t*)(Xbase + par * (2 * XB));
            const uint32_t* Xl = Xh + XB / 4;

            float C[25][4];
            #pragma unroll
            for (int nt = 0; nt < 25; nt++)
                #pragma unroll
                for (int j = 0; j < 4; j++) C[nt][j] = 0.0f;

            for (int ks = 0; ks < KSTEPS; ks++) {
                const int k0 = ks * 16;
                const int aoff = (((m0 + g) * KP + k0) >> 1) + t4;
                uint32_t ah[4], al[4];
                ah[0] = Xh[aoff];
                ah[1] = Xh[aoff + 4 * KP];
                ah[2] = Xh[aoff + 4];
                ah[3] = Xh[aoff + 4 * KP + 4];
                al[0] = Xl[aoff];
                al[1] = Xl[aoff + 4 * KP];
                al[2] = Xl[aoff + 4];
                al[3] = Xl[aoff + 4 * KP + 4];

                #pragma unroll
                for (int nt = 0; nt < 25; nt++) {
                    const int boff = (((nt * 8 + g) * KP + k0) >> 1) + t4;
                    uint32_t bh[2] = { Wh32[boff], Wh32[boff + 4] };
                    uint32_t bl[2] = { Wl32[boff], Wl32[boff + 4] };
                    mma16816(C[nt], ah, bh);
                    mma16816(C[nt], al, bh);
                    mma16816(C[nt], ah, bl);
                }
            }

            // epilogue: add bias, store fp32
            float* out0 = g_xp + (size_t)(tile * 128 + m0 + g) * G4 + hf * NH;
            float* out1 = out0 + 8 * G4;
            #pragma unroll
            for (int nt = 0; nt < 25; nt++) {
                int col = nt * 8 + t4 * 2;
                float2 b2 = *(float2*)(bs + col);
                *(float2*)(out0 + col) = make_float2(C[nt][0] + b2.x, C[nt][1] + b2.y);
                *(float2*)(out1 + col) = make_float2(C[nt][2] + b2.x, C[nt][3] + b2.y);
            }
        }
        par ^= 1;
    }
}

// ---------------- recurrent scan (unchanged, passing) ----------------
__global__ __launch_bounds__(400) void lstm_scan_kernel(
    const float* __restrict__ Whh, int mode)
{
    extern __shared__ float smf[];
    float* Ws = smf;                  // [100][400], k-major
    float* Hs = smf + HDIM * G4;      // [100][32]

    const int tid = threadIdx.x;
    const int b0  = blockIdx.x * 32;

    for (int i = tid; i < HDIM * G4; i += 400) {
        int g = i / HDIM, k = i - g * HDIM;
        Ws[k * G4 + g] = Whh[i];
    }
    for (int i = tid; i < HDIM * 32; i += 400) Hs[i] = 0.0f;
    __syncthreads();

    const int bi   = tid & 7;
    const int uj   = tid >> 3;
    const int bloc = bi * 4;

    float c[4][2];
    #pragma unroll
    for (int bb = 0; bb < 4; bb++) { c[bb][0] = 0.0f; c[bb][1] = 0.0f; }

    const float* wp = Ws + uj * 2;
    const float* hp = Hs + bloc;

    for (int t = 0; t < TDIM; t++) {
        float acc[4][4][2];
        #pragma unroll
        for (int bb = 0; bb < 4; bb++) {
            const float* xp = g_xp + ((size_t)(b0 + bloc + bb) * TDIM + t) * G4 + uj * 2;
            #pragma unroll
            for (int gt = 0; gt < 4; gt++) {
                float2 v = *(const float2*)(xp + gt * HDIM);
                acc[gt][bb][0] = v.x;
                acc[gt][bb][1] = v.y;
            }
        }
        #pragma unroll 2
        for (int k = 0; k < HDIM; k++) {
            float4 hv = *(const float4*)(hp + k * 32);
            float hva[4] = {hv.x, hv.y, hv.z, hv.w};
            #pragma unroll
            for (int gt = 0; gt < 4; gt++) {
                float2 wv = *(const float2*)(wp + k * G4 + gt * HDIM);
                #pragma unroll
                for (int bb = 0; bb < 4; bb++) {
                    acc[gt][bb][0] = fmaf(hva[bb], wv.x, acc[gt][bb][0]);
                    acc[gt][bb][1] = fmaf(hva[bb], wv.y, acc[gt][bb][1]);
                }
            }
        }
        __syncthreads();

        float hval[4][2];
        #pragma unroll
        for (int bb = 0; bb < 4; bb++) {
            #pragma unroll
            for (int uu = 0; uu < 2; uu++) {
                float iv = sigm(acc[0][bb][uu]);
                float fv = sigm(acc[1][bb][uu]);
                float gv = tanh_fast(acc[2][bb][uu]);
                float ov = sigm(acc[3][bb][uu]);
                float cv = fmaf(fv, c[bb][uu], iv * gv);
                c[bb][uu] = cv;
                hval[bb][uu] = ov * tanh_fast(cv);
            }
        }
        #pragma unroll
        for (int uu = 0; uu < 2; uu++) {
            float4 v = make_float4(hval[0][uu], hval[1][uu], hval[2][uu], hval[3][uu]);
            *(float4*)(Hs + (uj * 2 + uu) * 32 + bloc) = v;
        }
        if (mode == 1) {
            #pragma unroll
            for (int bb = 0; bb < 4; bb++) {
                float2 v = make_float2(fmaxf(hval[bb][0], 0.0f), fmaxf(hval[bb][1], 0.0f));
                *(float2*)(g_h1 + ((size_t)(b0 + bloc + bb) * TDIM + t) * HDIM + uj * 2) = v;
            }
        } else if (t == TDIM - 1) {
            #pragma unroll
            for (int bb = 0; bb < 4; bb++) {
                float2 v = make_float2(fmaxf(hval[bb][0], 0.0f), fmaxf(hval[bb][1], 0.0f));
                *(float2*)(g_last + (b0 + bloc + bb) * HDIM + uj * 2) = v;
            }
        }
        __syncthreads();
    }
}

// ---------------- head: fc(8) + softmax ----------------
__global__ void head_kernel(const float* __restrict__ wfc,
                            const float* __restrict__ bfc,
                            float* __restrict__ out)
{
    int b = blockIdx.x * blockDim.x + threadIdx.x;
    if (b >= BDIM) return;
    const float* lr = g_last + b * HDIM;
    float lo[NCLS];
    #pragma unroll
    for (int cc = 0; cc < NCLS; cc++) {
        float s = bfc[cc];
        const float* wr = wfc + cc * HDIM;
        for (int u = 0; u < HDIM; u++) s = fmaf(lr[u], wr[u], s);
        lo[cc] = s;
    }
    float m = lo[0];
    #pragma unroll
    for (int cc = 1; cc < NCLS; cc++) m = fmaxf(m, lo[cc]);
    float sum = 0.0f;
    #pragma unroll
    for (int cc = 0; cc < NCLS; cc++) { lo[cc] = __expf(lo[cc] - m); sum += lo[cc]; }
    float inv = __fdividef(1.0f, sum);
    #pragma unroll
    for (int cc = 0; cc < NCLS; cc++) out[b * NCLS + cc] = lo[cc] * inv;
}

// ---------------- launch ----------------
extern "C" void kernel_launch(void* const* d_in, const int* in_sizes, int n_in,
                              void* d_out, int out_size)
{
    (void)in_sizes; (void)n_in; (void)out_size;
    const float* x     = (const float*)d_in[0];
    const float* w_ih1 = (const float*)d_in[1];
    const float* w_hh1 = (const float*)d_in[2];
    const float* b_ih1 = (const float*)d_in[3];
    const float* b_hh1 = (const float*)d_in[4];
    const float* w_ih2 = (const float*)d_in[5];
    const float* w_hh2 = (const float*)d_in[6];
    const float* b_ih2 = (const float*)d_in[7];
    const float* b_hh2 = (const float*)d_in[8];
    const float* w_fc  = (const float*)d_in[9];
    const float* b_fc  = (const float*)d_in[10];

    // dynamic smem sizes: 1024 + 2*WB + 4*XB
    const int SZ64  = 1024 + 2 * (200 * 72  * 2) + 4 * (128 * 72  * 2);  // 132352
    const int SZ100 = 1024 + 2 * (200 * 120 * 2) + 4 * (128 * 120 * 2); // 219904
    const int SSC   = (HDIM * G4 + HDIM * 32) * 4;                       // 172800

    cudaFuncSetAttribute(xproj_mma<64>,    cudaFuncAttributeMaxDynamicSharedMemorySize, SZ64);
    cudaFuncSetAttribute(xproj_mma<100>,   cudaFuncAttributeMaxDynamicSharedMemorySize, SZ100);
    cudaFuncSetAttribute(lstm_scan_kernel, cudaFuncAttributeMaxDynamicSharedMemorySize, SSC);

    void* h1_ptr = nullptr;
    cudaGetSymbolAddress(&h1_ptr, g_h1);

    // layer 1
    xproj_mma<64><<<148, 384, SZ64>>>(x, w_ih1, b_ih1, b_hh1);
    lstm_scan_kernel<<<128, 400, SSC>>>(w_hh1, 1);
    // layer 2
    xproj_mma<100><<<148, 384, SZ100>>>((const float*)h1_ptr, w_ih2, b_ih2, b_hh2);
    lstm_scan_kernel<<<128, 400, SSC>>>(w_hh2, 2);
    // head
    head_kernel<<<(BDIM + 255) / 256, 256>>>(w_fc, b_fc, (float*)d_out);
}

// round 6
// speedup vs baseline: 1.8769x; 1.3868x over previous
#include <cuda_runtime.h>
#include <cuda_bf16.h>
#include <cstdint>
#include <cstddef>

// Problem dims
#define BDIM 4096
#define TDIM 128
#define DDIM 64
#define HDIM 100
#define G4   400          // 4*H
#define NCLS 8
#define M1   (BDIM * TDIM)   // 524288 rows

// ---------------- scratch (device globals; no allocation allowed) ----------
__device__ __align__(16) float g_xp[(size_t)M1 * G4];     // 800 MB, reused by both layers
__device__ __align__(16) float g_h1[(size_t)M1 * HDIM];   // 200 MB, relu(h) of layer 1
__device__ __align__(16) float g_last[BDIM * HDIM];       // relu(h_T) of layer 2

// ---------------- helpers ----------------
__device__ __forceinline__ float sigm(float x) {
    return __fdividef(1.0f, 1.0f + __expf(-x));
}

__device__ __forceinline__ uint32_t pack_bf2(float a, float b) {
    __nv_bfloat162 p = __floats2bfloat162_rn(a, b);
    return *reinterpret_cast<uint32_t*>(&p);
}

// m16n8k16 row.col bf16 MMA with fp32 accumulate (HMMA on Blackwell)
__device__ __forceinline__ void mma16816(float c[4], const uint32_t a[4], const uint32_t b[2]) {
    asm volatile(
        "mma.sync.aligned.m16n8k16.row.col.f32.bf16.bf16.f32 "
        "{%0,%1,%2,%3}, {%4,%5,%6,%7}, {%8,%9}, {%0,%1,%2,%3};"
        : "+f"(c[0]), "+f"(c[1]), "+f"(c[2]), "+f"(c[3])
        : "r"(a[0]), "r"(a[1]), "r"(a[2]), "r"(a[3]), "r"(b[0]), "r"(b[1]));
}

// ======================================================================
// Tensor-core input projection: g_xp = X @ W^T + (ba+bb)
// Columns emitted GATE-INTERLEAVED: col' = unit*4 + gate (units split in
// halves of 50 across blockIdx&1), so the scan can keep its loads coalesced.
// ======================================================================
template <int K>
__device__ __forceinline__ void convert_tile(const float* __restrict__ Xt,
                                             char* Hi, char* Lo, int t0, int nthr)
{
    constexpr int KP = (K == 64) ? 72 : 120;
    constexpr int KQ = K / 4;
    for (int i4 = t0; i4 < 128 * KQ; i4 += nthr) {
        int r = i4 / KQ, kq = i4 - r * KQ;
        float4 v = *(const float4*)(Xt + (size_t)r * K + kq * 4);
        float h0 = __bfloat162float(__float2bfloat16(v.x));
        float h1 = __bfloat162float(__float2bfloat16(v.y));
        float h2 = __bfloat162float(__float2bfloat16(v.z));
        float h3 = __bfloat162float(__float2bfloat16(v.w));
        uint32_t* ph = (uint32_t*)(Hi + (r * KP + kq * 4) * 2);
        uint32_t* pl = (uint32_t*)(Lo + (r * KP + kq * 4) * 2);
        ph[0] = pack_bf2(h0, h1);
        ph[1] = pack_bf2(h2, h3);
        pl[0] = pack_bf2(v.x - h0, v.y - h1);
        pl[1] = pack_bf2(v.z - h2, v.w - h3);
    }
}

template <int K>
__global__ __launch_bounds__(384) void xproj_mma(
    const float* __restrict__ X, const float* __restrict__ W,
    const float* __restrict__ ba, const float* __restrict__ bb)
{
    constexpr int KP     = (K == 64) ? 72 : 120;   // smem row stride (conflict-free)
    constexpr int KSTEPS = (K + 15) / 16;          // 4 or 7
    constexpr int NH     = 200;
    constexpr int WB     = NH  * KP * 2;
    constexpr int XB     = 128 * KP * 2;

    extern __shared__ char sm[];
    float* bs = (float*)sm;                        // [200] bias
    char* Whi = sm + 1024;
    char* Wlo = Whi + WB;
    char* Xbase = Wlo + WB;

    const int tid  = threadIdx.x;
    const int wid  = tid >> 5;
    const int lane = tid & 31;
    const int g    = lane >> 2;
    const int t4   = lane & 3;
    const int hf   = blockIdx.x & 1;
    const int cta  = blockIdx.x >> 1;

    {
        uint32_t* z = (uint32_t*)Whi;
        int tot = (2 * WB + 4 * XB) / 4;
        for (int i = tid; i < tot; i += 384) z[i] = 0;
    }
    __syncthreads();

    // convert W (hi/lo) + bias; smem slot n <-> W row gate*100 + (hf*50 + n/4)
    {
        constexpr int KQ = K / 4;
        for (int i4 = tid; i4 < NH * KQ; i4 += 384) {
            int n = i4 / KQ, kq = i4 - n * KQ;
            int unit = hf * 50 + (n >> 2);
            int gate = n & 3;
            float4 v = *(const float4*)(W + (size_t)(gate * HDIM + unit) * K + kq * 4);
            float h0 = __bfloat162float(__float2bfloat16(v.x));
            float h1 = __bfloat162float(__float2bfloat16(v.y));
            float h2 = __bfloat162float(__float2bfloat16(v.z));
            float h3 = __bfloat162float(__float2bfloat16(v.w));
            uint32_t* ph = (uint32_t*)(Whi + (n * KP + kq * 4) * 2);
            uint32_t* pl = (uint32_t*)(Wlo + (n * KP + kq * 4) * 2);
            ph[0] = pack_bf2(h0, h1);
            ph[1] = pack_bf2(h2, h3);
            pl[0] = pack_bf2(v.x - h0, v.y - h1);
            pl[1] = pack_bf2(v.z - h2, v.w - h3);
        }
        for (int n = tid; n < NH; n += 384) {
            int wrow = (n & 3) * HDIM + hf * 50 + (n >> 2);
            bs[n] = ba[wrow] + bb[wrow];
        }
    }
    convert_tile<K>(X + (size_t)cta * 128 * K, Xbase, Xbase + XB, tid, 384);

    const uint32_t* Wh32 = (const uint32_t*)Whi;
    const uint32_t* Wl32 = (const uint32_t*)Wlo;
    const int m0 = wid * 16;

    int par = 0;
    for (int tile = cta; tile < 4096; tile += 74) {
        __syncthreads();

        if (wid >= 8) {
            int nt = tile + 74;
            if (nt < 4096) {
                char* Hi = Xbase + (par ^ 1) * (2 * XB);
                convert_tile<K>(X + (size_t)nt * 128 * K, Hi, Hi + XB, tid - 256, 128);
            }
        } else {
            const uint32_t* Xh = (const uint32_t*)(Xbase + par * (2 * XB));
            const uint32_t* Xl = Xh + XB / 4;

            float C[25][4];
            #pragma unroll
            for (int nt = 0; nt < 25; nt++)
                #pragma unroll
                for (int j = 0; j < 4; j++) C[nt][j] = 0.0f;

            for (int ks = 0; ks < KSTEPS; ks++) {
                const int k0 = ks * 16;
                const int aoff = (((m0 + g) * KP + k0) >> 1) + t4;
                uint32_t ah[4], al[4];
                ah[0] = Xh[aoff];
                ah[1] = Xh[aoff + 4 * KP];
                ah[2] = Xh[aoff + 4];
                ah[3] = Xh[aoff + 4 * KP + 4];
                al[0] = Xl[aoff];
                al[1] = Xl[aoff + 4 * KP];
                al[2] = Xl[aoff + 4];
                al[3] = Xl[aoff + 4 * KP + 4];

                #pragma unroll
                for (int nt = 0; nt < 25; nt++) {
                    const int boff = (((nt * 8 + g) * KP + k0) >> 1) + t4;
                    uint32_t bh[2] = { Wh32[boff], Wh32[boff + 4] };
                    uint32_t bl[2] = { Wl32[boff], Wl32[boff + 4] };
                    mma16816(C[nt], ah, bh);
                    mma16816(C[nt], al, bh);
                    mma16816(C[nt], ah, bl);
                }
            }

            float* out0 = g_xp + (size_t)(tile * 128 + m0 + g) * G4 + hf * NH;
            float* out1 = out0 + 8 * G4;
            #pragma unroll
            for (int nt = 0; nt < 25; nt++) {
                int col = nt * 8 + t4 * 2;
                float2 b2 = *(float2*)(bs + col);
                *(float2*)(out0 + col) = make_float2(C[nt][0] + b2.x, C[nt][1] + b2.y);
                *(float2*)(out1 + col) = make_float2(C[nt][2] + b2.x, C[nt][3] + b2.y);
            }
        }
        par ^= 1;
    }
}

// ======================================================================
// Tensor-core recurrent scan.
// 128 blocks x 32 batch rows, 256 threads (8 warps = 2 m-tiles x 4 n-cols).
// Whh in smem bf16 hi/lo, gate-interleaved rows (n' = unit*4+gate), KP=120.
// h state in smem bf16 hi/lo [32 x 120]; c in registers.
// Per step: 3-term bf16-split m16n8k16 MMAs; lane-pair shfl combines gates.
// ======================================================================
#define SKP 120                      // smem K stride (elements)
#define SWB (G4 * SKP * 2)           // 96000 B per W buffer
#define SAB (32 * SKP * 2)           // 7680 B per h buffer

__global__ __launch_bounds__(256) void lstm_scan_mma(
    const float* __restrict__ Whh, int mode)
{
    extern __shared__ char sm[];
    char* Whi = sm;
    char* Wlo = Whi + SWB;
    char* Ahi = Wlo + SWB;
    char* Alo = Ahi + SAB;

    const int tid  = threadIdx.x;
    const int wid  = tid >> 5;
    const int lane = tid & 31;
    const int g    = lane >> 2;
    const int t4   = lane & 3;
    const int b0   = blockIdx.x * 32;

    // zero everything (covers k-padding; initial h = 0)
    {
        uint32_t* z = (uint32_t*)sm;
        int tot = (2 * SWB + 2 * SAB) / 4;
        for (int i = tid; i < tot; i += 256) z[i] = 0;
    }
    __syncthreads();

    // fill Whh hi/lo, gate-interleaved: slot n' = unit*4+gate <- row gate*100+unit
    for (int i4 = tid; i4 < G4 * (HDIM / 4); i4 += 256) {
        int n = i4 / (HDIM / 4), kq = i4 - n * (HDIM / 4);
        int unit = n >> 2, gate = n & 3;
        float4 v = *(const float4*)(Whh + (size_t)(gate * HDIM + unit) * HDIM + kq * 4);
        float h0 = __bfloat162float(__float2bfloat16(v.x));
        float h1 = __bfloat162float(__float2bfloat16(v.y));
        float h2 = __bfloat162float(__float2bfloat16(v.z));
        float h3 = __bfloat162float(__float2bfloat16(v.w));
        uint32_t* ph = (uint32_t*)(Whi + (n * SKP + kq * 4) * 2);
        uint32_t* pl = (uint32_t*)(Wlo + (n * SKP + kq * 4) * 2);
        ph[0] = pack_bf2(h0, h1);
        ph[1] = pack_bf2(h2, h3);
        pl[0] = pack_bf2(v.x - h0, v.y - h1);
        pl[1] = pack_bf2(v.z - h2, v.w - h3);
    }
    __syncthreads();

    const uint32_t* Wh32 = (const uint32_t*)Whi;
    const uint32_t* Wl32 = (const uint32_t*)Wlo;
    const uint32_t* Ah32 = (const uint32_t*)Ahi;
    const uint32_t* Al32 = (const uint32_t*)Alo;
    __nv_bfloat16* Ah16 = (__nv_bfloat16*)Ahi;
    __nv_bfloat16* Al16 = (__nv_bfloat16*)Alo;

    const int mi     = wid & 1;
    const int ncol   = wid >> 1;
    const int m0     = mi * 16;
    const int NT     = (ncol < 2) ? 13 : 12;
    const int tstart = (ncol < 2) ? ncol * 13 : 26 + (ncol - 2) * 12;
    const bool evn   = (t4 & 1) == 0;

    const int row0 = m0 + g;        // local rows handled by this thread
    const int row1 = row0 + 8;

    float c[13][2];
    #pragma unroll
    for (int nt = 0; nt < 13; nt++) { c[nt][0] = 0.0f; c[nt][1] = 0.0f; }

    const int nbase = (tstart * 8 + g) * (SKP / 2) + t4;   // uint32 units

    for (int t = 0; t < TDIM; t++) {
        // prefetch x-projection (gate-interleaved layout, coalesced float2)
        float2 xv0[13], xv1[13];
        {
            const float* p0 = g_xp + ((size_t)(b0 + row0) * TDIM + t) * G4 + tstart * 8 + t4 * 2;
            const float* p1 = g_xp + ((size_t)(b0 + row1) * TDIM + t) * G4 + tstart * 8 + t4 * 2;
            #pragma unroll
            for (int nt = 0; nt < 13; nt++) {
                if (nt < NT) {
                    xv0[nt] = *(const float2*)(p0 + nt * 8);
                    xv1[nt] = *(const float2*)(p1 + nt * 8);
                }
            }
        }

        float C[13][4];
        #pragma unroll
        for (int nt = 0; nt < 13; nt++)
            #pragma unroll
            for (int j = 0; j < 4; j++) C[nt][j] = 0.0f;

        #pragma unroll
        for (int ks = 0; ks < 7; ks++) {
            const int aoff = row0 * (SKP / 2) + ks * 8 + t4;
            uint32_t ah[4], al[4];
            ah[0] = Ah32[aoff];
            ah[1] = Ah32[aoff + 4 * SKP];
            ah[2] = Ah32[aoff + 4];
            ah[3] = Ah32[aoff + 4 * SKP + 4];
            al[0] = Al32[aoff];
            al[1] = Al32[aoff + 4 * SKP];
            al[2] = Al32[aoff + 4];
            al[3] = Al32[aoff + 4 * SKP + 4];

            #pragma unroll
            for (int nt = 0; nt < 13; nt++) {
                if (nt < NT) {
                    const int boff = nbase + nt * 8 * (SKP / 2) + ks * 8;
                    uint32_t bh[2] = { Wh32[boff], Wh32[boff + 4] };
                    uint32_t bl[2] = { Wl32[boff], Wl32[boff + 4] };
                    mma16816(C[nt], ah, bh);
                    mma16816(C[nt], al, bh);
                    mma16816(C[nt], ah, bl);
                }
            }
        }
        __syncthreads();   // all reads of h(t-1) done

        // gates -> c,h.  Lane pairs: even t4 holds (i,f), odd holds (g,o).
        #pragma unroll
        for (int nt = 0; nt < 13; nt++) {
            if (nt < NT) {
                const int u = (tstart + nt) * 2 + (t4 >> 1);   // unit index
                #pragma unroll
                for (int r = 0; r < 2; r++) {
                    float p0 = C[nt][2 * r]     + (r ? xv1[nt].x : xv0[nt].x);
                    float p1 = C[nt][2 * r + 1] + (r ? xv1[nt].y : xv0[nt].y);
                    // a0: even -> sigm(p0) [i]; odd -> tanh(p0) [g] via 2*sigm(2x)-1
                    float q0 = evn ? p0 : (p0 + p0);
                    float s  = sigm(q0);
                    float a0 = evn ? s : (s + s - 1.0f);
                    float a1 = sigm(p1);                       // even: f ; odd: o
                    float pa0 = __shfl_xor_sync(0xFFFFFFFFu, a0, 1);
                    float pa1 = __shfl_xor_sync(0xFFFFFFFFu, a1, 1);
                    float iv = evn ? a0  : pa0;
                    float fv = evn ? a1  : pa1;
                    float gv = evn ? pa0 : a0;
                    float ov = evn ? pa1 : a1;
                    float cn = fmaf(fv, c[nt][r], iv * gv);
                    c[nt][r] = cn;
                    float sc = sigm(cn + cn);
                    float hv = ov * (sc + sc - 1.0f);

                    if (evn) {
                        int lrow = r ? row1 : row0;
                        __nv_bfloat16 hh = __float2bfloat16(hv);
                        float hl = hv - __bfloat162float(hh);
                        Ah16[lrow * SKP + u] = hh;
                        Al16[lrow * SKP + u] = __float2bfloat16(hl);
                        if (mode == 1) {
                            g_h1[((size_t)(b0 + lrow) * TDIM + t) * HDIM + u] = fmaxf(hv, 0.0f);
                        } else if (t == TDIM - 1) {
                            g_last[(b0 + lrow) * HDIM + u] = fmaxf(hv, 0.0f);
                        }
                    }
                }
            }
        }
        __syncthreads();   // h(t) visible before next step's reads
    }
}

// ---------------- head: fc(8) + softmax ----------------
__global__ void head_kernel(const float* __restrict__ wfc,
                            const float* __restrict__ bfc,
                            float* __restrict__ out)
{
    int b = blockIdx.x * blockDim.x + threadIdx.x;
    if (b >= BDIM) return;
    const float* lr = g_last + b * HDIM;
    float lo[NCLS];
    #pragma unroll
    for (int cc = 0; cc < NCLS; cc++) {
        float s = bfc[cc];
        const float* wr = wfc + cc * HDIM;
        for (int u = 0; u < HDIM; u++) s = fmaf(lr[u], wr[u], s);
        lo[cc] = s;
    }
    float m = lo[0];
    #pragma unroll
    for (int cc = 1; cc < NCLS; cc++) m = fmaxf(m, lo[cc]);
    float sum = 0.0f;
    #pragma unroll
    for (int cc = 0; cc < NCLS; cc++) { lo[cc] = __expf(lo[cc] - m); sum += lo[cc]; }
    float inv = __fdividef(1.0f, sum);
    #pragma unroll
    for (int cc = 0; cc < NCLS; cc++) out[b * NCLS + cc] = lo[cc] * inv;
}

// ---------------- launch ----------------
extern "C" void kernel_launch(void* const* d_in, const int* in_sizes, int n_in,
                              void* d_out, int out_size)
{
    (void)in_sizes; (void)n_in; (void)out_size;
    const float* x     = (const float*)d_in[0];
    const float* w_ih1 = (const float*)d_in[1];
    const float* w_hh1 = (const float*)d_in[2];
    const float* b_ih1 = (const float*)d_in[3];
    const float* b_hh1 = (const float*)d_in[4];
    const float* w_ih2 = (const float*)d_in[5];
    const float* w_hh2 = (const float*)d_in[6];
    const float* b_ih2 = (const float*)d_in[7];
    const float* b_hh2 = (const float*)d_in[8];
    const float* w_fc  = (const float*)d_in[9];
    const float* b_fc  = (const float*)d_in[10];

    const int SZ64  = 1024 + 2 * (200 * 72  * 2) + 4 * (128 * 72  * 2);  // 132352
    const int SZ100 = 1024 + 2 * (200 * 120 * 2) + 4 * (128 * 120 * 2); // 219904
    const int SSC   = 2 * SWB + 2 * SAB;                                 // 207360

    cudaFuncSetAttribute(xproj_mma<64>,  cudaFuncAttributeMaxDynamicSharedMemorySize, SZ64);
    cudaFuncSetAttribute(xproj_mma<100>, cudaFuncAttributeMaxDynamicSharedMemorySize, SZ100);
    cudaFuncSetAttribute(lstm_scan_mma,  cudaFuncAttributeMaxDynamicSharedMemorySize, SSC);

    void* h1_ptr = nullptr;
    cudaGetSymbolAddress(&h1_ptr, g_h1);

    // layer 1
    xproj_mma<64><<<148, 384, SZ64>>>(x, w_ih1, b_ih1, b_hh1);
    lstm_scan_mma<<<128, 256, SSC>>>(w_hh1, 1);
    // layer 2
    xproj_mma<100><<<148, 384, SZ100>>>((const float*)h1_ptr, w_ih2, b_ih2, b_hh2);
    lstm_scan_mma<<<128, 256, SSC>>>(w_hh2, 2);
    // head
    head_kernel<<<(BDIM + 255) / 256, 256>>>(w_fc, b_fc, (float*)d_out);
}

// round 8
// speedup vs baseline: 2.0408x; 1.0873x over previous
#include <cuda_runtime.h>
#include <cuda_bf16.h>
#include <cstdint>
#include <cstddef>

// Problem dims
#define BDIM 4096
#define TDIM 128
#define DDIM 64
#define HDIM 100
#define G4   400          // 4*H
#define NCLS 8
#define M1   (BDIM * TDIM)   // 524288 rows

// ---------------- scratch (device globals; no allocation allowed) ----------
__device__ __align__(16) float g_xp[(size_t)M1 * G4];     // 800 MB, reused by both layers
__device__ __align__(16) float g_h1[(size_t)M1 * HDIM];   // 200 MB, relu(h) of layer 1
__device__ __align__(16) float g_last[BDIM * HDIM];       // relu(h_T) of layer 2

// ---------------- helpers ----------------
__device__ __forceinline__ float sigm(float x) {
    return __fdividef(1.0f, 1.0f + __expf(-x));
}

__device__ __forceinline__ uint32_t pack_bf2(float a, float b) {
    __nv_bfloat162 p = __floats2bfloat162_rn(a, b);
    return *reinterpret_cast<uint32_t*>(&p);
}

// m16n8k16 row.col bf16 MMA with fp32 accumulate (HMMA on Blackwell)
__device__ __forceinline__ void mma16816(float c[4], const uint32_t a[4], const uint32_t b[2]) {
    asm volatile(
        "mma.sync.aligned.m16n8k16.row.col.f32.bf16.bf16.f32 "
        "{%0,%1,%2,%3}, {%4,%5,%6,%7}, {%8,%9}, {%0,%1,%2,%3};"
        : "+f"(c[0]), "+f"(c[1]), "+f"(c[2]), "+f"(c[3])
        : "r"(a[0]), "r"(a[1]), "r"(a[2]), "r"(a[3]), "r"(b[0]), "r"(b[1]));
}

// ======================================================================
// Tensor-core input projection: g_xp = X @ W^T + (ba+bb)
// Columns emitted GATE-INTERLEAVED: col' = unit*4 + gate (units split in
// halves of 50 across blockIdx&1), so the scan can keep its loads coalesced.
// ======================================================================
template <int K>
__device__ __forceinline__ void convert_tile(const float* __restrict__ Xt,
                                             char* Hi, char* Lo, int t0, int nthr)
{
    constexpr int KP = (K == 64) ? 72 : 120;
    constexpr int KQ = K / 4;
    for (int i4 = t0; i4 < 128 * KQ; i4 += nthr) {
        int r = i4 / KQ, kq = i4 - r * KQ;
        float4 v = *(const float4*)(Xt + (size_t)r * K + kq * 4);
        float h0 = __bfloat162float(__float2bfloat16(v.x));
        float h1 = __bfloat162float(__float2bfloat16(v.y));
        float h2 = __bfloat162float(__float2bfloat16(v.z));
        float h3 = __bfloat162float(__float2bfloat16(v.w));
        uint32_t* ph = (uint32_t*)(Hi + (r * KP + kq * 4) * 2);
        uint32_t* pl = (uint32_t*)(Lo + (r * KP + kq * 4) * 2);
        ph[0] = pack_bf2(h0, h1);
        ph[1] = pack_bf2(h2, h3);
        pl[0] = pack_bf2(v.x - h0, v.y - h1);
        pl[1] = pack_bf2(v.z - h2, v.w - h3);
    }
}

template <int K>
__global__ __launch_bounds__(384) void xproj_mma(
    const float* __restrict__ X, const float* __restrict__ W,
    const float* __restrict__ ba, const float* __restrict__ bb)
{
    constexpr int KP     = (K == 64) ? 72 : 120;   // smem row stride (conflict-free)
    constexpr int KSTEPS = (K + 15) / 16;          // 4 or 7
    constexpr int NH     = 200;
    constexpr int WB     = NH  * KP * 2;
    constexpr int XB     = 128 * KP * 2;

    extern __shared__ char sm[];
    float* bs = (float*)sm;                        // [200] bias
    char* Whi = sm + 1024;
    char* Wlo = Whi + WB;
    char* Xbase = Wlo + WB;

    const int tid  = threadIdx.x;
    const int wid  = tid >> 5;
    const int lane = tid & 31;
    const int g    = lane >> 2;
    const int t4   = lane & 3;
    const int hf   = blockIdx.x & 1;
    const int cta  = blockIdx.x >> 1;

    {
        uint32_t* z = (uint32_t*)Whi;
        int tot = (2 * WB + 4 * XB) / 4;
        for (int i = tid; i < tot; i += 384) z[i] = 0;
    }
    __syncthreads();

    // convert W (hi/lo) + bias; smem slot n <-> W row gate*100 + (hf*50 + n/4)
    {
        constexpr int KQ = K / 4;
        for (int i4 = tid; i4 < NH * KQ; i4 += 384) {
            int n = i4 / KQ, kq = i4 - n * KQ;
            int unit = hf * 50 + (n >> 2);
            int gate = n & 3;
            float4 v = *(const float4*)(W + (size_t)(gate * HDIM + unit) * K + kq * 4);
            float h0 = __bfloat162float(__float2bfloat16(v.x));
            float h1 = __bfloat162float(__float2bfloat16(v.y));
            float h2 = __bfloat162float(__float2bfloat16(v.z));
            float h3 = __bfloat162float(__float2bfloat16(v.w));
            uint32_t* ph = (uint32_t*)(Whi + (n * KP + kq * 4) * 2);
            uint32_t* pl = (uint32_t*)(Wlo + (n * KP + kq * 4) * 2);
            ph[0] = pack_bf2(h0, h1);
            ph[1] = pack_bf2(h2, h3);
            pl[0] = pack_bf2(v.x - h0, v.y - h1);
            pl[1] = pack_bf2(v.z - h2, v.w - h3);
        }
        for (int n = tid; n < NH; n += 384) {
            int wrow = (n & 3) * HDIM + hf * 50 + (n >> 2);
            bs[n] = ba[wrow] + bb[wrow];
        }
    }
    convert_tile<K>(X + (size_t)cta * 128 * K, Xbase, Xbase + XB, tid, 384);

    const uint32_t* Wh32 = (const uint32_t*)Whi;
    const uint32_t* Wl32 = (const uint32_t*)Wlo;
    const int m0 = wid * 16;

    int par = 0;
    for (int tile = cta; tile < 4096; tile += 74) {
        __syncthreads();

        if (wid >= 8) {
            int nt = tile + 74;
            if (nt < 4096) {
                char* Hi = Xbase + (par ^ 1) * (2 * XB);
                convert_tile<K>(X + (size_t)nt * 128 * K, Hi, Hi + XB, tid - 256, 128);
            }
        } else {
            const uint32_t* Xh = (const uint32_t*)(Xbase + par * (2 * XB));
            const uint32_t* Xl = Xh + XB / 4;

            float C[25][4];
            #pragma unroll
            for (int nt = 0; nt < 25; nt++)
                #pragma unroll
                for (int j = 0; j < 4; j++) C[nt][j] = 0.0f;

            for (int ks = 0; ks < KSTEPS; ks++) {
                const int k0 = ks * 16;
                const int aoff = (((m0 + g) * KP + k0) >> 1) + t4;
                uint32_t ah[4], al[4];
                ah[0] = Xh[aoff];
                ah[1] = Xh[aoff + 4 * KP];
                ah[2] = Xh[aoff + 4];
                ah[3] = Xh[aoff + 4 * KP + 4];
                al[0] = Xl[aoff];
                al[1] = Xl[aoff + 4 * KP];
                al[2] = Xl[aoff + 4];
                al[3] = Xl[aoff + 4 * KP + 4];

                #pragma unroll
                for (int nt = 0; nt < 25; nt++) {
                    const int boff = (((nt * 8 + g) * KP + k0) >> 1) + t4;
                    uint32_t bh[2] = { Wh32[boff], Wh32[boff + 4] };
                    uint32_t bl[2] = { Wl32[boff], Wl32[boff + 4] };
                    mma16816(C[nt], ah, bh);
                    mma16816(C[nt], al, bh);
                    mma16816(C[nt], ah, bl);
                }
            }

            float* out0 = g_xp + (size_t)(tile * 128 + m0 + g) * G4 + hf * NH;
            float* out1 = out0 + 8 * G4;
            #pragma unroll
            for (int nt = 0; nt < 25; nt++) {
                int col = nt * 8 + t4 * 2;
                float2 b2 = *(float2*)(bs + col);
                *(float2*)(out0 + col) = make_float2(C[nt][0] + b2.x, C[nt][1] + b2.y);
                *(float2*)(out1 + col) = make_float2(C[nt][2] + b2.x, C[nt][3] + b2.y);
            }
        }
        par ^= 1;
    }
}

// ======================================================================
// Tensor-core recurrent scan, v2.
// 128 blocks x 32 batch rows, 512 threads (16 warps = 2 m-tiles x 8 n-cols,
// NT = 7/7/6/6/6/6/6/6 n8-tiles). Whh smem bf16 hi/lo gate-interleaved.
// h state DOUBLE-BUFFERED bf16 hi/lo -> ONE barrier per step.
// MMA accumulators initialized directly from g_xp loads (no xv registers).
// ======================================================================
#define SKP 120                      // smem K stride (elements)
#define SWB (G4 * SKP * 2)           // 96000 B per W buffer
#define SAB (32 * SKP * 2)           // 7680 B per h buffer

__global__ __launch_bounds__(512) void lstm_scan_mma(
    const float* __restrict__ Whh, int mode)
{
    extern __shared__ char sm[];
    char* Whi   = sm;
    char* Wlo   = Whi + SWB;
    char* Abase = Wlo + SWB;         // 2 parity buffers x (hi, lo)

    const int tid  = threadIdx.x;
    const int wid  = tid >> 5;
    const int lane = tid & 31;
    const int g    = lane >> 2;
    const int t4   = lane & 3;
    const int b0   = blockIdx.x * 32;

    // zero everything (covers k-padding; initial h = 0 in parity-0 buffer)
    {
        uint32_t* z = (uint32_t*)sm;
        int tot = (2 * SWB + 4 * SAB) / 4;
        for (int i = tid; i < tot; i += 512) z[i] = 0;
    }
    __syncthreads();

    // fill Whh hi/lo, gate-interleaved: slot n' = unit*4+gate <- row gate*100+unit
    for (int i4 = tid; i4 < G4 * (HDIM / 4); i4 += 512) {
        int n = i4 / (HDIM / 4), kq = i4 - n * (HDIM / 4);
        int unit = n >> 2, gate = n & 3;
        float4 v = *(const float4*)(Whh + (size_t)(gate * HDIM + unit) * HDIM + kq * 4);
        float h0 = __bfloat162float(__float2bfloat16(v.x));
        float h1 = __bfloat162float(__float2bfloat16(v.y));
        float h2 = __bfloat162float(__float2bfloat16(v.z));
        float h3 = __bfloat162float(__float2bfloat16(v.w));
        uint32_t* ph = (uint32_t*)(Whi + (n * SKP + kq * 4) * 2);
        uint32_t* pl = (uint32_t*)(Wlo + (n * SKP + kq * 4) * 2);
        ph[0] = pack_bf2(h0, h1);
        ph[1] = pack_bf2(h2, h3);
        pl[0] = pack_bf2(v.x - h0, v.y - h1);
        pl[1] = pack_bf2(v.z - h2, v.w - h3);
    }
    __syncthreads();

    const uint32_t* Wh32 = (const uint32_t*)Whi;
    const uint32_t* Wl32 = (const uint32_t*)Wlo;

    const int mi     = wid & 1;
    const int ncol   = wid >> 1;                    // 0..7
    const int m0     = mi * 16;
    const int NT     = (ncol < 2) ? 7 : 6;
    const int tstart = (ncol < 2) ? ncol * 7 : 14 + (ncol - 2) * 6;
    const bool evn   = (t4 & 1) == 0;

    const int row0 = m0 + g;
    const int row1 = row0 + 8;

    float c[7][2];
    #pragma unroll
    for (int nt = 0; nt < 7; nt++) { c[nt][0] = 0.0f; c[nt][1] = 0.0f; }

    const int nbase = (tstart * 8 + g) * (SKP / 2) + t4;   // uint32 units

    int par = 0;
    for (int t = 0; t < TDIM; t++) {
        const uint32_t* Ah32 = (const uint32_t*)(Abase + par * (2 * SAB));
        const uint32_t* Al32 = Ah32 + SAB / 4;
        __nv_bfloat16* AhW = (__nv_bfloat16*)(Abase + (par ^ 1) * (2 * SAB));
        __nv_bfloat16* AlW = AhW + SAB / 2;

        // accumulators initialized from x-projection (gate-interleaved, coalesced)
        float C[7][4];
        {
            const float* p0 = g_xp + ((size_t)(b0 + row0) * TDIM + t) * G4 + tstart * 8 + t4 * 2;
            const float* p1 = g_xp + ((size_t)(b0 + row1) * TDIM + t) * G4 + tstart * 8 + t4 * 2;
            #pragma unroll
            for (int nt = 0; nt < 7; nt++) {
                if (nt < NT) {
                    float2 v0 = *(const float2*)(p0 + nt * 8);
                    float2 v1 = *(const float2*)(p1 + nt * 8);
                    C[nt][0] = v0.x; C[nt][1] = v0.y;
                    C[nt][2] = v1.x; C[nt][3] = v1.y;
                }
            }
        }

        #pragma unroll
        for (int ks = 0; ks < 7; ks++) {
            const int aoff = row0 * (SKP / 2) + ks * 8 + t4;
            uint32_t ah[4], al[4];
            ah[0] = Ah32[aoff];
            ah[1] = Ah32[aoff + 4 * SKP];
            ah[2] = Ah32[aoff + 4];
            ah[3] = Ah32[aoff + 4 * SKP + 4];
            al[0] = Al32[aoff];
            al[1] = Al32[aoff + 4 * SKP];
            al[2] = Al32[aoff + 4];
            al[3] = Al32[aoff + 4 * SKP + 4];

            #pragma unroll
            for (int nt = 0; nt < 7; nt++) {
                if (nt < NT) {
                    const int boff = nbase + nt * 8 * (SKP / 2) + ks * 8;
                    uint32_t bh[2] = { Wh32[boff], Wh32[boff + 4] };
                    uint32_t bl[2] = { Wl32[boff], Wl32[boff + 4] };
                    mma16816(C[nt], ah, bh);
                    mma16816(C[nt], al, bh);
                    mma16816(C[nt], ah, bl);
                }
            }
        }

        // gates -> c,h.  Lane pairs: even t4 holds (i,f), odd holds (g,o).
        #pragma unroll
        for (int nt = 0; nt < 7; nt++) {
            if (nt < NT) {
                const int u = (tstart + nt) * 2 + (t4 >> 1);   // unit index
                #pragma unroll
                for (int r = 0; r < 2; r++) {
                    float p0 = C[nt][2 * r];
                    float p1 = C[nt][2 * r + 1];
                    float q0 = evn ? p0 : (p0 + p0);
                    float s  = sigm(q0);
                    float a0 = evn ? s : (s + s - 1.0f);       // even: i ; odd: g
                    float a1 = sigm(p1);                       // even: f ; odd: o
                    float pa0 = __shfl_xor_sync(0xFFFFFFFFu, a0, 1);
                    float pa1 = __shfl_xor_sync(0xFFFFFFFFu, a1, 1);
                    float iv = evn ? a0  : pa0;
                    float fv = evn ? a1  : pa1;
                    float gv = evn ? pa0 : a0;
                    float ov = evn ? pa1 : a1;
                    float cn = fmaf(fv, c[nt][r], iv * gv);
                    c[nt][r] = cn;
                    float sc = sigm(cn + cn);
                    float hv = ov * (sc + sc - 1.0f);

                    if (evn) {
                        int lrow = r ? row1 : row0;
                        __nv_bfloat16 hh = __float2bfloat16(hv);
                        float hl = hv - __bfloat162float(hh);
                        AhW[lrow * SKP + u] = hh;
                        AlW[lrow * SKP + u] = __float2bfloat16(hl);
                        if (mode == 1) {
                            g_h1[((size_t)(b0 + lrow) * TDIM + t) * HDIM + u] = fmaxf(hv, 0.0f);
                        } else if (t == TDIM - 1) {
                            g_last[(b0 + lrow) * HDIM + u] = fmaxf(hv, 0.0f);
                        }
                    }
                }
            }
        }
        par ^= 1;
        __syncthreads();   // h(t) in buf[par] visible before next step's reads
    }
}

// ---------------- head: fc(8) + softmax ----------------
__global__ void head_kernel(const float* __restrict__ wfc,
                            const float* __restrict__ bfc,
                            float* __restrict__ out)
{
    int b = blockIdx.x * blockDim.x + threadIdx.x;
    if (b >= BDIM) return;
    const float* lr = g_last + b * HDIM;
    float lo[NCLS];
    #pragma unroll
    for (int cc = 0; cc < NCLS; cc++) {
        float s = bfc[cc];
        const float* wr = wfc + cc * HDIM;
        for (int u = 0; u < HDIM; u++) s = fmaf(lr[u], wr[u], s);
        lo[cc] = s;
    }
    float m = lo[0];
    #pragma unroll
    for (int cc = 1; cc < NCLS; cc++) m = fmaxf(m, lo[cc]);
    float sum = 0.0f;
    #pragma unroll
    for (int cc = 0; cc < NCLS; cc++) { lo[cc] = __expf(lo[cc] - m); sum += lo[cc]; }
    float inv = __fdividef(1.0f, sum);
    #pragma unroll
    for (int cc = 0; cc < NCLS; cc++) out[b * NCLS + cc] = lo[cc] * inv;
}

// ---------------- launch ----------------
extern "C" void kernel_launch(void* const* d_in, const int* in_sizes, int n_in,
                              void* d_out, int out_size)
{
    (void)in_sizes; (void)n_in; (void)out_size;
    const float* x     = (const float*)d_in[0];
    const float* w_ih1 = (const float*)d_in[1];
    const float* w_hh1 = (const float*)d_in[2];
    const float* b_ih1 = (const float*)d_in[3];
    const float* b_hh1 = (const float*)d_in[4];
    const float* w_ih2 = (const float*)d_in[5];
    const float* w_hh2 = (const float*)d_in[6];
    const float* b_ih2 = (const float*)d_in[7];
    const float* b_hh2 = (const float*)d_in[8];
    const float* w_fc  = (const float*)d_in[9];
    const float* b_fc  = (const float*)d_in[10];

    const int SZ64  = 1024 + 2 * (200 * 72  * 2) + 4 * (128 * 72  * 2);  // 132352
    const int SZ100 = 1024 + 2 * (200 * 120 * 2) + 4 * (128 * 120 * 2); // 219904
    const int SSC   = 2 * SWB + 4 * SAB;                                 // 222720

    cudaFuncSetAttribute(xproj_mma<64>,  cudaFuncAttributeMaxDynamicSharedMemorySize, SZ64);
    cudaFuncSetAttribute(xproj_mma<100>, cudaFuncAttributeMaxDynamicSharedMemorySize, SZ100);
    cudaFuncSetAttribute(lstm_scan_mma,  cudaFuncAttributeMaxDynamicSharedMemorySize, SSC);

    void* h1_ptr = nullptr;
    cudaGetSymbolAddress(&h1_ptr, g_h1);

    // layer 1
    xproj_mma<64><<<148, 384, SZ64>>>(x, w_ih1, b_ih1, b_hh1);
    lstm_scan_mma<<<128, 512, SSC>>>(w_hh1, 1);
    // layer 2
    xproj_mma<100><<<148, 384, SZ100>>>((const float*)h1_ptr, w_ih2, b_ih2, b_hh2);
    lstm_scan_mma<<<128, 512, SSC>>>(w_hh2, 2);
    // head
    head_kernel<<<(BDIM + 255) / 256, 256>>>(w_fc, b_fc, (float*)d_out);
}